// round 5
// baseline (speedup 1.0000x reference)
#include <cuda_runtime.h>
#include <cuda_bf16.h>
#include <cooperative_groups.h>
#include <cstdint>

namespace cg = cooperative_groups;

// Problem constants (fixed by the dataset)
#define BB    8        // batch
#define TT    4096     // time steps
#define FF    512      // input features
#define CC    128      // reduced input
#define UU    256      // LSTM units
#define OO    64       // output features
#define G4    1024     // 4*U

// -------- scratch (device globals; no allocation allowed) --------
__device__ float g_xr[(size_t)BB * TT * CC];   // 16 MB
__device__ float g_z [(size_t)BB * TT * G4];   // 128 MB
__device__ float g_hs[(size_t)BB * TT * UU];   // 32 MB

// ---------------- packed f32x2 helpers ----------------
__device__ __forceinline__ unsigned long long packf2(float lo, float hi) {
    unsigned long long r;
    asm("mov.b64 %0, {%1, %2};" : "=l"(r) : "f"(lo), "f"(hi));
    return r;
}
__device__ __forceinline__ void fma2(unsigned long long& d,
                                     unsigned long long a,
                                     unsigned long long b) {
    asm("fma.rn.f32x2 %0, %1, %2, %0;" : "+l"(d) : "l"(a), "l"(b));
}
__device__ __forceinline__ float reduce2(unsigned long long d) {
    float lo, hi;
    asm("mov.b64 {%0, %1}, %2;" : "=f"(lo), "=f"(hi) : "l"(d));
    return lo + hi;
}

// ---------------- fast activations ----------------
__device__ __forceinline__ float fsig(float x) {
    return 1.0f / (1.0f + __expf(-x));
}
__device__ __forceinline__ float ftanh(float x) {
    x = fminf(fmaxf(x, -15.0f), 15.0f);
    float e = __expf(2.0f * x);
    return (e - 1.0f) / (e + 1.0f);
}

// ---------------- split cluster barrier (arrive = release, wait = acquire) ----------------
__device__ __forceinline__ void cluster_arrive() {
    asm volatile("barrier.cluster.arrive.aligned;" ::: "memory");
}
__device__ __forceinline__ void cluster_wait() {
    asm volatile("barrier.cluster.wait.aligned;" ::: "memory");
}

// =====================================================================
// Generic fp32 tiled GEMM: C[M,N] = A[M,K] * B[K,N] + bias[N]
// =====================================================================
template <int BM, int BN, int BK, int TM, int TN, int NT>
__global__ void __launch_bounds__(NT)
gemm_bias_kernel(const float* __restrict__ A, const float* __restrict__ Bm,
                 const float* __restrict__ bias, float* __restrict__ C,
                 int M, int N, int K) {
    __shared__ __align__(16) float As[BK][BM];
    __shared__ __align__(16) float Bs[BK][BN];

    const int tx = threadIdx.x % (BN / TN);
    const int ty = threadIdx.x / (BN / TN);
    const int rowBase = blockIdx.y * BM;
    const int colBase = blockIdx.x * BN;

    float acc[TM][TN];
#pragma unroll
    for (int i = 0; i < TM; i++)
#pragma unroll
        for (int j = 0; j < TN; j++) acc[i][j] = 0.0f;

    for (int k0 = 0; k0 < K; k0 += BK) {
#pragma unroll
        for (int idx = threadIdx.x; idx < BM * BK / 4; idx += NT) {
            int r  = idx / (BK / 4);
            int kc = (idx % (BK / 4)) * 4;
            float4 v = *(const float4*)&A[(size_t)(rowBase + r) * K + k0 + kc];
            As[kc + 0][r] = v.x;
            As[kc + 1][r] = v.y;
            As[kc + 2][r] = v.z;
            As[kc + 3][r] = v.w;
        }
#pragma unroll
        for (int idx = threadIdx.x; idx < BK * BN / 4; idx += NT) {
            int kr = idx / (BN / 4);
            int cc = (idx % (BN / 4)) * 4;
            *(float4*)&Bs[kr][cc] =
                *(const float4*)&Bm[(size_t)(k0 + kr) * N + colBase + cc];
        }
        __syncthreads();

#pragma unroll
        for (int kk = 0; kk < BK; kk++) {
            float ra[TM], rb[TN];
#pragma unroll
            for (int i = 0; i < TM; i++) ra[i] = As[kk][ty * TM + i];
#pragma unroll
            for (int j = 0; j < TN; j++) rb[j] = Bs[kk][tx * TN + j];
#pragma unroll
            for (int i = 0; i < TM; i++)
#pragma unroll
                for (int j = 0; j < TN; j++)
                    acc[i][j] = fmaf(ra[i], rb[j], acc[i][j]);
        }
        __syncthreads();
    }

#pragma unroll
    for (int i = 0; i < TM; i++) {
        int row = rowBase + ty * TM + i;
#pragma unroll
        for (int j = 0; j < TN; j += 4) {
            int col = colBase + tx * TN + j;
            float4 b4 = *(const float4*)&bias[col];
            float4 o;
            o.x = acc[i][j + 0] + b4.x;
            o.y = acc[i][j + 1] + b4.y;
            o.z = acc[i][j + 2] + b4.z;
            o.w = acc[i][j + 3] + b4.w;
            *(float4*)&C[(size_t)row * N + col] = o;
        }
    }
}

// =====================================================================
// LSTM recurrence. 8 clusters (one per batch) x 8 CTAs x 256 threads.
// c = tid>>1 (gate-column), s = tid&1 (K-half); cross-K reduce = shfl.
// h exchange: cooperative-groups DSMEM stores (the mechanism that ran
// clean in R1), but with the cluster barrier SPLIT: arrive right after
// the epilogue stores, wait at the top of the next step. Double-buffered
// hbuf bounds skew to one step.
// =====================================================================
#define LSTM_NTH 256
#define CLSZ     8

__global__ void __cluster_dims__(CLSZ, 1, 1) __launch_bounds__(LSTM_NTH, 1)
lstm_kernel(const float* __restrict__ rec_kernel) {
    cg::cluster_group cluster = cg::this_cluster();
    const int rank  = cluster.block_rank();        // 0..7
    const int batch = blockIdx.x / CLSZ;
    const int tid   = threadIdx.x;

    const int c  = tid >> 1;    // gate-column within this CTA's 128 cols
    const int s  = tid & 1;     // K-half
    const int g  = c >> 5;      // gate: 0=i,1=f,2=g,3=o
    const int lu = c & 31;      // local unit
    const int u  = rank * 32 + lu;
    const int colIdx = (g << 8) + u;

    __shared__ __align__(16) float hbuf[2][UU];
    __shared__ float act[128];

    // ---- weight slice into registers as packed row-pairs ----
    // w2[2m]   covers k = s*128 + 4m, 4m+1 ; w2[2m+1] covers 4m+2, 4m+3
    unsigned long long w2[64];
#pragma unroll
    for (int m = 0; m < 64; m++) {
        float a = rec_kernel[(size_t)(s * 128 + 4 * (m >> 1) + 2 * (m & 1))     * G4 + colIdx];
        float b = rec_kernel[(size_t)(s * 128 + 4 * (m >> 1) + 2 * (m & 1) + 1) * G4 + colIdx];
        w2[m] = packf2(a, b);
    }

    // warp 0: peer h-slot pointers (our unit slot in every peer, both buffers)
    float* dstH[2][CLSZ];
    if (tid < 32) {
#pragma unroll
        for (int r = 0; r < CLSZ; r++) {
            dstH[0][r] = (float*)cluster.map_shared_rank((void*)&hbuf[0][rank * 32 + tid], r);
            dstH[1][r] = (float*)cluster.map_shared_rank((void*)&hbuf[1][rank * 32 + tid], r);
        }
    }

    // zero both h buffers
    for (int i = tid; i < 2 * UU; i += LSTM_NTH) ((float*)hbuf)[i] = 0.0f;
    cluster_arrive();   // pre-loop arrive: pairs with the t=0 wait below

    const float* zbase = g_z + (size_t)batch * TT * G4 + colIdx;
    float* hsbase = g_hs + (size_t)batch * TT * UU;

    float zin = (s == 0) ? zbase[0] : 0.0f;
    float cst = 0.0f;             // cell state (warp-0 lanes)

#pragma unroll 1
    for (int t = 0; t < TT; t++) {
        const int p = t & 1;

        cluster_wait();           // h[p] complete cluster-wide (acquire)

        // prefetch next z (one full step of latency hiding)
        float znext = 0.0f;
        if (s == 0 && t + 1 < TT) znext = __ldg(&zbase[(size_t)(t + 1) * G4]);

        // ---- dot: my K-half of h[p] vs my weight column; 4 indep chains ----
        unsigned long long a0 = 0ULL, a1 = 0ULL, a2 = 0ULL, a3 = 0ULL;
        const ulonglong2* h2 = (const ulonglong2*)hbuf[p];
#pragma unroll
        for (int m = 0; m < 32; m += 2) {
            ulonglong2 hv0 = h2[s * 32 + m];
            ulonglong2 hv1 = h2[s * 32 + m + 1];
            fma2(a0, w2[2 * m],     hv0.x);
            fma2(a1, w2[2 * m + 1], hv0.y);
            fma2(a2, w2[2 * m + 2], hv1.x);
            fma2(a3, w2[2 * m + 3], hv1.y);
        }
        float v = reduce2(a0) + reduce2(a1) + reduce2(a2) + reduce2(a3);
        v += __shfl_xor_sync(0xffffffffu, v, 1);

        if (s == 0) {
            float z = v + zin;
            zin = znext;
            act[c] = (g == 2) ? ftanh(z) : fsig(z);
        }
        __syncthreads();

        if (tid < 32) {
            float ai = act[tid];
            float af = act[32 + tid];
            float ag = act[64 + tid];
            float ao = act[96 + tid];
            cst = af * cst + ai * ag;
            float hval = ao * ftanh(cst);
            if (t + 1 < TT) {
                const int q = p ^ 1;             // next buffer
#pragma unroll
                for (int r = 0; r < CLSZ; r++)
                    *dstH[q][r] = hval;          // DSMEM stores (release via arrive)
            }
            hsbase[(size_t)t * UU + rank * 32 + tid] = hval;
        }
        if (t + 1 < TT) {
            cluster_arrive();     // release our h[q] stores; overlap with next wait
        }
    }
    cluster.sync();   // keep SMEM alive until all remote traffic settled
}

// =====================================================================
// Launch
// =====================================================================
extern "C" void kernel_launch(void* const* d_in, const int* in_sizes, int n_in,
                              void* d_out, int out_size) {
    const float* x          = (const float*)d_in[0];
    const float* w_in       = (const float*)d_in[1];
    const float* b_in       = (const float*)d_in[2];
    const float* kern       = (const float*)d_in[3];
    const float* rec_kernel = (const float*)d_in[4];
    const float* bias       = (const float*)d_in[5];
    const float* w_out      = (const float*)d_in[6];
    const float* b_out      = (const float*)d_in[7];
    float* out = (float*)d_out;

    float* xr = nullptr;
    float* zz = nullptr;
    float* hs = nullptr;
    cudaGetSymbolAddress((void**)&xr, g_xr);
    cudaGetSymbolAddress((void**)&zz, g_z);
    cudaGetSymbolAddress((void**)&hs, g_hs);

    const int M = BB * TT;  // 32768

    gemm_bias_kernel<128, 128, 16, 8, 8, 256>
        <<<dim3(CC / 128, M / 128), 256>>>(x, w_in, b_in, xr, M, CC, FF);

    gemm_bias_kernel<128, 128, 16, 8, 8, 256>
        <<<dim3(G4 / 128, M / 128), 256>>>(xr, kern, bias, zz, M, G4, CC);

    lstm_kernel<<<BB * CLSZ, LSTM_NTH>>>(rec_kernel);

    gemm_bias_kernel<128, 64, 8, 8, 4, 256>
        <<<dim3(OO / 64, M / 128), 256>>>(hs, w_out, b_out, out, M, OO, UU);
}

// round 6
// speedup vs baseline: 1.1978x; 1.1978x over previous
#include <cuda_runtime.h>
#include <cuda_bf16.h>
#include <cooperative_groups.h>
#include <cstdint>

namespace cg = cooperative_groups;

// Problem constants (fixed by the dataset)
#define BB    8        // batch
#define TT    4096     // time steps
#define FF    512      // input features
#define CC    128      // reduced input
#define UU    256      // LSTM units
#define OO    64       // output features
#define G4    1024     // 4*U

// -------- scratch (device globals; no allocation allowed) --------
__device__ float g_xr[(size_t)BB * TT * CC];   // 16 MB
__device__ float g_z [(size_t)BB * TT * G4];   // 128 MB
__device__ float g_hs[(size_t)BB * TT * UU];   // 32 MB

// ---------------- packed f32x2 helpers ----------------
__device__ __forceinline__ unsigned long long packf2(float lo, float hi) {
    unsigned long long r;
    asm("mov.b64 %0, {%1, %2};" : "=l"(r) : "f"(lo), "f"(hi));
    return r;
}
__device__ __forceinline__ void fma2(unsigned long long& d,
                                     unsigned long long a,
                                     unsigned long long b) {
    asm("fma.rn.f32x2 %0, %1, %2, %0;" : "+l"(d) : "l"(a), "l"(b));
}
__device__ __forceinline__ float reduce2(unsigned long long d) {
    float lo, hi;
    asm("mov.b64 {%0, %1}, %2;" : "=f"(lo), "=f"(hi) : "l"(d));
    return lo + hi;
}

// ---------------- fast activations ----------------
__device__ __forceinline__ float fsig(float x) {
    return 1.0f / (1.0f + __expf(-x));
}
__device__ __forceinline__ float ftanh(float x) {
    x = fminf(fmaxf(x, -15.0f), 15.0f);
    float e = __expf(2.0f * x);
    return (e - 1.0f) / (e + 1.0f);
}

// =====================================================================
// Generic fp32 tiled GEMM: C[M,N] = A[M,K] * B[K,N] + bias[N]
// (EXACT R1 configuration — BK=8 — the config measured at 4675us total)
// =====================================================================
template <int BM, int BN, int BK, int TM, int TN, int NT>
__global__ void __launch_bounds__(NT)
gemm_bias_kernel(const float* __restrict__ A, const float* __restrict__ Bm,
                 const float* __restrict__ bias, float* __restrict__ C,
                 int M, int N, int K) {
    __shared__ __align__(16) float As[BK][BM];
    __shared__ __align__(16) float Bs[BK][BN];

    const int tx = threadIdx.x % (BN / TN);
    const int ty = threadIdx.x / (BN / TN);
    const int rowBase = blockIdx.y * BM;
    const int colBase = blockIdx.x * BN;

    float acc[TM][TN];
#pragma unroll
    for (int i = 0; i < TM; i++)
#pragma unroll
        for (int j = 0; j < TN; j++) acc[i][j] = 0.0f;

    for (int k0 = 0; k0 < K; k0 += BK) {
#pragma unroll 2
        for (int idx = threadIdx.x; idx < BM * BK / 4; idx += NT) {
            int r  = idx / (BK / 4);
            int kc = (idx % (BK / 4)) * 4;
            float4 v = *(const float4*)&A[(size_t)(rowBase + r) * K + k0 + kc];
            As[kc + 0][r] = v.x;
            As[kc + 1][r] = v.y;
            As[kc + 2][r] = v.z;
            As[kc + 3][r] = v.w;
        }
#pragma unroll 2
        for (int idx = threadIdx.x; idx < BK * BN / 4; idx += NT) {
            int kr = idx / (BN / 4);
            int cc = (idx % (BN / 4)) * 4;
            *(float4*)&Bs[kr][cc] =
                *(const float4*)&Bm[(size_t)(k0 + kr) * N + colBase + cc];
        }
        __syncthreads();

#pragma unroll
        for (int kk = 0; kk < BK; kk++) {
            float ra[TM], rb[TN];
#pragma unroll
            for (int i = 0; i < TM; i++) ra[i] = As[kk][ty * TM + i];
#pragma unroll
            for (int j = 0; j < TN; j++) rb[j] = Bs[kk][tx * TN + j];
#pragma unroll
            for (int i = 0; i < TM; i++)
#pragma unroll
                for (int j = 0; j < TN; j++)
                    acc[i][j] = fmaf(ra[i], rb[j], acc[i][j]);
        }
        __syncthreads();
    }

#pragma unroll
    for (int i = 0; i < TM; i++) {
        int row = rowBase + ty * TM + i;
#pragma unroll
        for (int j = 0; j < TN; j += 4) {
            int col = colBase + tx * TN + j;
            float4 b4 = *(const float4*)&bias[col];
            float4 o;
            o.x = acc[i][j + 0] + b4.x;
            o.y = acc[i][j + 1] + b4.y;
            o.z = acc[i][j + 2] + b4.z;
            o.w = acc[i][j + 3] + b4.w;
            *(float4*)&C[(size_t)row * N + col] = o;
        }
    }
}

// =====================================================================
// LSTM recurrence. 8 clusters (one per batch) x 8 CTAs x 256 threads.
// Mechanism = R1's proven fused cluster.sync; compute = improved:
//   c = tid>>1 (gate-column), s = tid&1 (K-half); cross-K = shfl.xor 1
//   4 independent FFMA2 accumulator chains; ulonglong2 h loads;
//   one __syncthreads per step; g_hs STG moved after cluster.sync.
// =====================================================================
#define LSTM_NTH 256
#define CLSZ     8

__global__ void __cluster_dims__(CLSZ, 1, 1) __launch_bounds__(LSTM_NTH, 1)
lstm_kernel(const float* __restrict__ rec_kernel) {
    cg::cluster_group cluster = cg::this_cluster();
    const int rank  = cluster.block_rank();        // 0..7
    const int batch = blockIdx.x / CLSZ;
    const int tid   = threadIdx.x;

    const int c  = tid >> 1;    // gate-column within this CTA's 128 cols
    const int s  = tid & 1;     // K-half
    const int g  = c >> 5;      // gate: 0=i,1=f,2=g,3=o
    const int lu = c & 31;      // local unit
    const int u  = rank * 32 + lu;
    const int colIdx = (g << 8) + u;

    __shared__ __align__(16) float hbuf[2][UU];
    __shared__ float act[128];

    // ---- weight slice into registers as packed row-pairs ----
    // w2[2m]   covers k = s*128 + 4m, 4m+1 ; w2[2m+1] covers 4m+2, 4m+3
    unsigned long long w2[64];
#pragma unroll
    for (int m = 0; m < 64; m++) {
        float a = rec_kernel[(size_t)(s * 128 + 4 * (m >> 1) + 2 * (m & 1))     * G4 + colIdx];
        float b = rec_kernel[(size_t)(s * 128 + 4 * (m >> 1) + 2 * (m & 1) + 1) * G4 + colIdx];
        w2[m] = packf2(a, b);
    }

    // warp 0: peer h-slot pointers (our unit slot in every peer, both buffers)
    float* dstH[2][CLSZ];
    if (tid < 32) {
#pragma unroll
        for (int r = 0; r < CLSZ; r++) {
            dstH[0][r] = (float*)cluster.map_shared_rank((void*)&hbuf[0][rank * 32 + tid], r);
            dstH[1][r] = (float*)cluster.map_shared_rank((void*)&hbuf[1][rank * 32 + tid], r);
        }
    }

    // zero both h buffers
    for (int i = tid; i < 2 * UU; i += LSTM_NTH) ((float*)hbuf)[i] = 0.0f;
    cluster.sync();   // buffers zeroed cluster-wide

    const float* zbase = g_z + (size_t)batch * TT * G4 + colIdx;
    float* hsbase = g_hs + (size_t)batch * TT * UU;

    float zin = (s == 0) ? zbase[0] : 0.0f;
    float cst = 0.0f;             // cell state (warp-0 lanes)

#pragma unroll 1
    for (int t = 0; t < TT; t++) {
        const int p = t & 1;

        // prefetch next z (one full step of latency hiding)
        float znext = 0.0f;
        if (s == 0 && t + 1 < TT) znext = __ldg(&zbase[(size_t)(t + 1) * G4]);

        // ---- dot: my K-half of h[p] vs my weight column; 4 indep chains ----
        unsigned long long a0 = 0ULL, a1 = 0ULL, a2 = 0ULL, a3 = 0ULL;
        const ulonglong2* h2 = (const ulonglong2*)hbuf[p];
#pragma unroll
        for (int m = 0; m < 32; m += 2) {
            ulonglong2 hv0 = h2[s * 32 + m];
            ulonglong2 hv1 = h2[s * 32 + m + 1];
            fma2(a0, w2[2 * m],     hv0.x);
            fma2(a1, w2[2 * m + 1], hv0.y);
            fma2(a2, w2[2 * m + 2], hv1.x);
            fma2(a3, w2[2 * m + 3], hv1.y);
        }
        float v = reduce2(a0) + reduce2(a1) + reduce2(a2) + reduce2(a3);
        v += __shfl_xor_sync(0xffffffffu, v, 1);

        if (s == 0) {
            float z = v + zin;
            zin = znext;
            act[c] = (g == 2) ? ftanh(z) : fsig(z);
        }
        __syncthreads();

        float hval = 0.0f;
        if (tid < 32) {
            float ai = act[tid];
            float af = act[32 + tid];
            float ag = act[64 + tid];
            float ao = act[96 + tid];
            cst = af * cst + ai * ag;
            hval = ao * ftanh(cst);
            const int q = p ^ 1;                 // next buffer
#pragma unroll
            for (int r = 0; r < CLSZ; r++)
                *dstH[q][r] = hval;              // DSMEM stores, released by sync
        }
        cluster.sync();                          // h[q] complete cluster-wide
        if (tid < 32) {
            // off the barrier's critical path: nothing reads g_hs until kernel 4
            hsbase[(size_t)t * UU + rank * 32 + tid] = hval;
        }
    }
}

// =====================================================================
// Launch
// =====================================================================
extern "C" void kernel_launch(void* const* d_in, const int* in_sizes, int n_in,
                              void* d_out, int out_size) {
    const float* x          = (const float*)d_in[0];
    const float* w_in       = (const float*)d_in[1];
    const float* b_in       = (const float*)d_in[2];
    const float* kern       = (const float*)d_in[3];
    const float* rec_kernel = (const float*)d_in[4];
    const float* bias       = (const float*)d_in[5];
    const float* w_out      = (const float*)d_in[6];
    const float* b_out      = (const float*)d_in[7];
    float* out = (float*)d_out;

    float* xr = nullptr;
    float* zz = nullptr;
    float* hs = nullptr;
    cudaGetSymbolAddress((void**)&xr, g_xr);
    cudaGetSymbolAddress((void**)&zz, g_z);
    cudaGetSymbolAddress((void**)&hs, g_hs);

    const int M = BB * TT;  // 32768

    gemm_bias_kernel<128, 128, 8, 8, 8, 256>
        <<<dim3(CC / 128, M / 128), 256>>>(x, w_in, b_in, xr, M, CC, FF);

    gemm_bias_kernel<128, 128, 8, 8, 8, 256>
        <<<dim3(G4 / 128, M / 128), 256>>>(xr, kern, bias, zz, M, G4, CC);

    lstm_kernel<<<BB * CLSZ, LSTM_NTH>>>(rec_kernel);

    gemm_bias_kernel<128, 64, 8, 8, 4, 256>
        <<<dim3(OO / 64, M / 128), 256>>>(hs, w_out, b_out, out, M, OO, UU);
}